// round 14
// baseline (speedup 1.0000x reference)
#include <cuda_runtime.h>
#include <cuda_bf16.h>
#include <cstdint>

// ---------------------------------------------------------------------------
// JointRetriveDeformHead — round 13
//  * PointNet H2 (64->128) moved onto mma.sync as well (3-limb bf16):
//    A = H1 limbs [32pt x 64k] (scalar H1 -> split -> smem tiles),
//    B = prepacked W2 limbs [128ch x 64k] (global, L1-resident),
//    D = [pt x ch] -> bias+relu+split -> BH/BL tiles (H3 input, unchanged).
//    Cuts the dominant ~900-instr scalar H2 loop to ~250 instr.
//  * Kernel fusion: k_prep (transpose+W3/W2 prepack+SC1+P1, role by blockIdx)
//    and k_fcdist (fc + distances + top-10). 9 launches -> 5.
//  * decode_mlp is now launch #4 -> profiled next round.
// ---------------------------------------------------------------------------

#define B_      64
#define S_      1024
#define D_      256
#define KRET    10
#define NPART   16
#define NPAR    96
#define PSRC3   1536

__device__ float g_pool[2 * B_ * D_];
__device__ float g_T   [B_ * D_];
__device__ int   g_idx [B_ * KRET];
__device__ float g_par [B_ * KRET * NPAR];
__device__ float g_SC1 [S_ * D_];
__device__ float g_P1  [S_ * NPART * D_];
__device__ float g_varT[D_ * S_];
__device__ float g_rscT[D_ * S_];
__device__ unsigned short g_A3h[2 * 256 * 128];   // W3^T hi limb [enc][ch][k]
__device__ unsigned short g_A3l[2 * 256 * 128];   // W3^T lo limb
__device__ unsigned short g_A2h[2 * 128 * 64];    // W2^T hi limb [enc][ch][k]
__device__ unsigned short g_A2l[2 * 128 * 64];    // W2^T lo limb

typedef unsigned long long u64;

__device__ __forceinline__ u64 pk(float lo, float hi) {
    u64 r; asm("mov.b64 %0,{%1,%2};" : "=l"(r) : "f"(lo), "f"(hi)); return r;
}
__device__ __forceinline__ void upk(u64 v, float& lo, float& hi) {
    asm("mov.b64 {%0,%1},%2;" : "=f"(lo), "=f"(hi) : "l"(v));
}
__device__ __forceinline__ u64 fma2(u64 a, u64 b, u64 c) {
    u64 d; asm("fma.rn.f32x2 %0,%1,%2,%3;" : "=l"(d) : "l"(a), "l"(b), "l"(c)); return d;
}
__device__ __forceinline__ void split_bf16(float v, unsigned short& h, unsigned short& l) {
    __nv_bfloat16 bh = __float2bfloat16(v);
    float fh = __bfloat162float(bh);
    __nv_bfloat16 bl = __float2bfloat16(v - fh);
    h = __bfloat16_as_ushort(bh);
    l = __bfloat16_as_ushort(bl);
}

#define MMA16816(d0,d1,d2,d3,a0,a1,a2,a3,b0,b1) \
    asm volatile("mma.sync.aligned.m16n8k16.row.col.f32.bf16.bf16.f32 " \
        "{%0,%1,%2,%3}, {%4,%5,%6,%7}, {%8,%9}, {%0,%1,%2,%3};" \
        : "+f"(d0),"+f"(d1),"+f"(d2),"+f"(d3) \
        : "r"(a0),"r"(a1),"r"(a2),"r"(a3),"r"(b0),"r"(b1))

// pointnet dynamic smem layout (bytes)
#define OFF_ALO 0          // W3 lo limb: u16[256][136] = 69632
#define OFF_BH  69632      // H2-out hi:  u16[32][136]  = 8704
#define OFF_BL  78336      // H2-out lo:  u16[32][136]  = 8704
#define OFF_A1H 87040      // H1 hi limb: u32[32][68]   = 8704
#define OFF_A1L 95744      // H1 lo limb: u32[32][68]   = 8704
#define OFF_X   104448     // X: float[3][32]           = 384
#define SMEMSZ  104832

// ---------------------------------------------------------------------------
// k_prep — fused prep work, role by blockIdx.x. grid 1728, 256 threads.
//  [0,256)    transpose var/rsc -> [k][s]
//  [256,576)  W3/W2 limb prepack
//  [576,704)  SC1 (8 sources per block)
//  [704,1728) P1 (1 source per block)
// ---------------------------------------------------------------------------
__global__ __launch_bounds__(256)
void k_prep(const float* __restrict__ var,  const float* __restrict__ rsc,
            const float* __restrict__ teW3, const float* __restrict__ reW3,
            const float* __restrict__ teW2, const float* __restrict__ reW2,
            const float* __restrict__ src_codes,
            const float* __restrict__ decW1, const float* __restrict__ decb1,
            const float* __restrict__ part_latent)
{
    __shared__ __align__(16) char prepsm[8448];
    const int bid = blockIdx.x, t = threadIdx.x;

    if (bid < 256) {
        // ---- transpose 32x32 tiles ----
        float (*tv)[33] = (float(*)[33])prepsm;
        float (*tr)[33] = (float(*)[33])(prepsm + 4224);
        const int tx = t & 31, ty = t >> 5;
        const int s0 = (bid & 31) * 32, k0 = (bid >> 5) * 32;
        #pragma unroll
        for (int jj = 0; jj < 4; ++jj) {
            int s = s0 + ty + jj * 8;
            tv[ty + jj * 8][tx] = var[s * D_ + k0 + tx];
            tr[ty + jj * 8][tx] = rsc[s * D_ + k0 + tx];
        }
        __syncthreads();
        #pragma unroll
        for (int jj = 0; jj < 4; ++jj) {
            int k = k0 + ty + jj * 8;
            g_varT[k * S_ + s0 + tx] = tv[tx][ty + jj * 8];
            g_rscT[k * S_ + s0 + tx] = tr[tx][ty + jj * 8];
        }
    } else if (bid < 576) {
        // ---- weight limb prepack ----
        int idx = (bid - 256) * 256 + t;       // [0, 81920)
        if (idx < 65536) {
            int enc = idx >> 15;
            int r   = idx & 32767;
            int ch  = r >> 7;
            int k   = r & 127;
            const float* W3 = enc ? reW3 : teW3;
            float w = W3[k * 256 + ch];
            unsigned short h, l;
            split_bf16(w, h, l);
            g_A3h[idx] = h;
            g_A3l[idx] = l;
        } else {
            int r = idx - 65536;               // [0, 16384)
            int enc = r >> 13;
            int r2  = r & 8191;
            int ch  = r2 >> 6;
            int k   = r2 & 63;
            const float* W2 = enc ? reW2 : teW2;
            float w = W2[k * 128 + ch];
            unsigned short h, l;
            split_bf16(w, h, l);
            g_A2h[enc * 8192 + ch * 64 + k] = h;
            g_A2l[enc * 8192 + ch * 64 + k] = l;
        }
    } else if (bid < 704) {
        // ---- SC1: 8 sources per block ----
        float (*scs)[256] = (float(*)[256])prepsm;
        const int s0 = (bid - 576) * 8;
        #pragma unroll
        for (int q = 0; q < 8; ++q)
            scs[q][t] = src_codes[(s0 + q) * 256 + t];
        __syncthreads();
        float acc[8];
        float bb = decb1[t];
        #pragma unroll
        for (int q = 0; q < 8; ++q) acc[q] = bb;
        #pragma unroll 4
        for (int i = 0; i < 256; ++i) {
            float w = decW1[(256 + i) * 256 + t];
            #pragma unroll
            for (int q = 0; q < 8; ++q)
                acc[q] = fmaf(scs[q][i], w, acc[q]);
        }
        #pragma unroll
        for (int q = 0; q < 8; ++q)
            g_SC1[(s0 + q) * 256 + t] = acc[q];
    } else {
        // ---- P1 ----
        float (*part)[32] = (float(*)[32])prepsm;
        const int s = bid - 704;
        ((float*)part)[t]       = part_latent[s * (NPART * 32) + t];
        ((float*)part)[t + 256] = part_latent[s * (NPART * 32) + t + 256];
        __syncthreads();
        float wt[32];
        #pragma unroll
        for (int i = 0; i < 32; ++i)
            wt[i] = decW1[(512 + i) * 256 + t];
        #pragma unroll 2
        for (int p = 0; p < NPART; ++p) {
            float v = 0.f;
            #pragma unroll
            for (int i = 0; i < 32; ++i)
                v = fmaf(part[p][i], wt[i], v);
            g_P1[(s * NPART + p) * 256 + t] = v;
        }
    }
}

// ---------------------------------------------------------------------------
// Kernel 1: PointNet. grid (64,2), 256 threads. H2 and H3 both on mma.sync.
// ---------------------------------------------------------------------------
__global__ __launch_bounds__(256, 1)
void k_pointnet(const float* __restrict__ noc,
                const float* __restrict__ teW1, const float* __restrict__ teb1,
                const float* __restrict__ teb2, const float* __restrict__ teb3,
                const float* __restrict__ reW1, const float* __restrict__ reb1,
                const float* __restrict__ reb2, const float* __restrict__ reb3)
{
    extern __shared__ char smem[];
    const int b = blockIdx.x;
    const int enc = blockIdx.y;
    const float* W1 = enc ? reW1 : teW1; const float* b1 = enc ? reb1 : teb1;
    const float* b2 = enc ? reb2 : teb2; const float* b3 = enc ? reb3 : teb3;

    const int t = threadIdx.x;
    const int warp = t >> 5, lane = t & 31;
    const int g = lane >> 2, j = lane & 3;

    unsigned short* ALO = (unsigned short*)(smem + OFF_ALO);
    unsigned short* BHs = (unsigned short*)(smem + OFF_BH);
    unsigned short* BLs = (unsigned short*)(smem + OFF_BL);
    uint32_t* A1H = (uint32_t*)(smem + OFF_A1H);
    uint32_t* A1L = (uint32_t*)(smem + OFF_A1L);
    float* Xf = (float*)(smem + OFF_X);
    const uint32_t* ALO32 = (const uint32_t*)ALO;
    const uint32_t* BH32  = (const uint32_t*)BHs;
    const uint32_t* BL32  = (const uint32_t*)BLs;

    // ---- stage W3-lo limb into padded smem ----
    {
        const uint4* src = (const uint4*)(g_A3l + enc * 32768);
        #pragma unroll
        for (int i = 0; i < 16; ++i)
            *(uint4*)(ALO + t * 136 + i * 8) = src[t * 16 + i];
    }

    // ---- W3-hi fragments -> registers (64 u32/thread) ----
    uint32_t ahi[64];
    {
        const uint32_t* AH = (const uint32_t*)(g_A3h + enc * 32768); // [256][64]
        #pragma unroll
        for (int mt = 0; mt < 2; ++mt) {
            const int r0 = warp * 32 + mt * 16 + g;
            #pragma unroll
            for (int ks = 0; ks < 8; ++ks) {
                const int fi = (mt * 8 + ks) * 4;
                ahi[fi + 0] = AH[r0 * 64 + j + 8 * ks];
                ahi[fi + 1] = AH[(r0 + 8) * 64 + j + 8 * ks];
                ahi[fi + 2] = AH[r0 * 64 + j + 4 + 8 * ks];
                ahi[fi + 3] = AH[(r0 + 8) * 64 + j + 4 + 8 * ks];
            }
        }
    }

    // ---- H1 per-thread constants: thread (pt = t&31, w2 = t>>5) owns 8 chs ----
    const int pt = t & 31, w2 = t >> 5;
    float w1x[8], w1y[8], w1z[8], b1v[8];
    #pragma unroll
    for (int cc = 0; cc < 8; ++cc) {
        int ch = w2 * 8 + cc;
        w1x[cc] = W1[ch]; w1y[cc] = W1[64 + ch]; w1z[cc] = W1[128 + ch];
        b1v[cc] = b1[ch];
    }

    // ---- H2-MMA warp roles + b2 biases ----
    const int mt2 = warp >> 2;            // pt tile (0..1)
    const int ntb = (warp & 3) * 4;       // ch n8-tile base (x4)
    float bias2[4][2];
    #pragma unroll
    for (int nt = 0; nt < 4; ++nt) {
        int ch0 = (ntb + nt) * 8 + 2 * j;
        bias2[nt][0] = b2[ch0];
        bias2[nt][1] = b2[ch0 + 1];
    }
    const uint32_t* W2H32 = (const uint32_t*)(g_A2h + enc * 8192);  // [128][32]
    const uint32_t* W2L32 = (const uint32_t*)(g_A2l + enc * 8192);

    float dmax[4] = { -1e30f, -1e30f, -1e30f, -1e30f };

    #pragma unroll 1
    for (int chunk = 0; chunk < 32; ++chunk) {
        __syncthreads();
        if (t < 96) {
            int c = t >> 5, p = t & 31;
            Xf[c * 32 + p] = noc[b * 3072 + c * 1024 + chunk * 32 + p];
        }
        __syncthreads();

        // ---- H1: 3 -> 64, split to bf16 limbs, pack into A1 tiles ----
        {
            float x0 = Xf[pt], x1 = Xf[32 + pt], x2 = Xf[64 + pt];
            uint32_t hpk[4], lpk[4];
            #pragma unroll
            for (int cc = 0; cc < 8; ++cc) {
                float v = fmaxf(fmaf(x0, w1x[cc], fmaf(x1, w1y[cc],
                                fmaf(x2, w1z[cc], b1v[cc]))), 0.f);
                unsigned short h, l;
                split_bf16(v, h, l);
                if (cc & 1) { hpk[cc >> 1] |= (uint32_t)h << 16; lpk[cc >> 1] |= (uint32_t)l << 16; }
                else        { hpk[cc >> 1] = h;                  lpk[cc >> 1] = l; }
            }
            *(u64*)&A1H[pt * 68 + w2 * 4]     = (u64)hpk[0] | ((u64)hpk[1] << 32);
            *(u64*)&A1H[pt * 68 + w2 * 4 + 2] = (u64)hpk[2] | ((u64)hpk[3] << 32);
            *(u64*)&A1L[pt * 68 + w2 * 4]     = (u64)lpk[0] | ((u64)lpk[1] << 32);
            *(u64*)&A1L[pt * 68 + w2 * 4 + 2] = (u64)lpk[2] | ((u64)lpk[3] << 32);
        }
        __syncthreads();

        // ---- H2 via MMA: D[32pt x 128ch] = H1limbs x W2limbs (3 passes) ----
        {
            float dd[4][4];
            #pragma unroll
            for (int nt = 0; nt < 4; ++nt)
                #pragma unroll
                for (int e = 0; e < 4; ++e) dd[nt][e] = 0.f;

            const int r2 = mt2 * 16 + g;
            #pragma unroll
            for (int ks = 0; ks < 4; ++ks) {
                uint32_t ah0 = A1H[r2 * 68 + j + 8 * ks];
                uint32_t ah1 = A1H[(r2 + 8) * 68 + j + 8 * ks];
                uint32_t ah2 = A1H[r2 * 68 + j + 4 + 8 * ks];
                uint32_t ah3 = A1H[(r2 + 8) * 68 + j + 4 + 8 * ks];
                uint32_t al0 = A1L[r2 * 68 + j + 8 * ks];
                uint32_t al1 = A1L[(r2 + 8) * 68 + j + 8 * ks];
                uint32_t al2 = A1L[r2 * 68 + j + 4 + 8 * ks];
                uint32_t al3 = A1L[(r2 + 8) * 68 + j + 4 + 8 * ks];
                #pragma unroll
                for (int nt = 0; nt < 4; ++nt) {
                    const int nr = ((ntb + nt) * 8 + g) * 32;
                    uint32_t bh0 = W2H32[nr + j + 8 * ks];
                    uint32_t bh1 = W2H32[nr + j + 4 + 8 * ks];
                    uint32_t bl0 = W2L32[nr + j + 8 * ks];
                    uint32_t bl1 = W2L32[nr + j + 4 + 8 * ks];
                    MMA16816(dd[nt][0], dd[nt][1], dd[nt][2], dd[nt][3],
                             ah0, ah1, ah2, ah3, bh0, bh1);
                    MMA16816(dd[nt][0], dd[nt][1], dd[nt][2], dd[nt][3],
                             ah0, ah1, ah2, ah3, bl0, bl1);
                    MMA16816(dd[nt][0], dd[nt][1], dd[nt][2], dd[nt][3],
                             al0, al1, al2, al3, bh0, bh1);
                }
            }

            // epilogue: bias + relu + split -> BH/BL tiles [pt][ch]
            const int pt0 = mt2 * 16 + g;
            #pragma unroll
            for (int nt = 0; nt < 4; ++nt) {
                const int ch0 = (ntb + nt) * 8 + 2 * j;
                unsigned short h0, l0, h1, l1;
                split_bf16(fmaxf(dd[nt][0] + bias2[nt][0], 0.f), h0, l0);
                split_bf16(fmaxf(dd[nt][1] + bias2[nt][1], 0.f), h1, l1);
                *(uint32_t*)((char*)BHs + pt0 * 272 + ch0 * 2) = (uint32_t)h0 | ((uint32_t)h1 << 16);
                *(uint32_t*)((char*)BLs + pt0 * 272 + ch0 * 2) = (uint32_t)l0 | ((uint32_t)l1 << 16);
                split_bf16(fmaxf(dd[nt][2] + bias2[nt][0], 0.f), h0, l0);
                split_bf16(fmaxf(dd[nt][3] + bias2[nt][1], 0.f), h1, l1);
                *(uint32_t*)((char*)BHs + (pt0 + 8) * 272 + ch0 * 2) = (uint32_t)h0 | ((uint32_t)h1 << 16);
                *(uint32_t*)((char*)BLs + (pt0 + 8) * 272 + ch0 * 2) = (uint32_t)l0 | ((uint32_t)l1 << 16);
            }
        }
        __syncthreads();

        // ---- H3 via MMA (unchanged): D[256ch x 32pt] ----
        float d[2][4][4];
        #pragma unroll
        for (int mt = 0; mt < 2; ++mt)
            #pragma unroll
            for (int nt = 0; nt < 4; ++nt)
                #pragma unroll
                for (int e = 0; e < 4; ++e) d[mt][nt][e] = 0.f;

        #pragma unroll
        for (int ks = 0; ks < 8; ++ks) {
            uint32_t bh0[4], bh1[4], bl0[4], bl1[4];
            #pragma unroll
            for (int nt = 0; nt < 4; ++nt) {
                const uint32_t* BHrow = BH32 + (nt * 8 + g) * 68;
                const uint32_t* BLrow = BL32 + (nt * 8 + g) * 68;
                bh0[nt] = BHrow[j + 8 * ks];
                bh1[nt] = BHrow[j + 4 + 8 * ks];
                bl0[nt] = BLrow[j + 8 * ks];
                bl1[nt] = BLrow[j + 4 + 8 * ks];
            }
            #pragma unroll
            for (int mt = 0; mt < 2; ++mt) {
                const int fi = (mt * 8 + ks) * 4;
                uint32_t a0 = ahi[fi], a1 = ahi[fi+1], a2 = ahi[fi+2], a3 = ahi[fi+3];
                #pragma unroll
                for (int nt = 0; nt < 4; ++nt) {
                    MMA16816(d[mt][nt][0], d[mt][nt][1], d[mt][nt][2], d[mt][nt][3],
                             a0, a1, a2, a3, bh0[nt], bh1[nt]);
                    MMA16816(d[mt][nt][0], d[mt][nt][1], d[mt][nt][2], d[mt][nt][3],
                             a0, a1, a2, a3, bl0[nt], bl1[nt]);
                }
                const int r0 = warp * 32 + mt * 16 + g;
                uint32_t l0 = ALO32[r0 * 68 + j + 8 * ks];
                uint32_t l1 = ALO32[(r0 + 8) * 68 + j + 8 * ks];
                uint32_t l2 = ALO32[r0 * 68 + j + 4 + 8 * ks];
                uint32_t l3 = ALO32[(r0 + 8) * 68 + j + 4 + 8 * ks];
                #pragma unroll
                for (int nt = 0; nt < 4; ++nt)
                    MMA16816(d[mt][nt][0], d[mt][nt][1], d[mt][nt][2], d[mt][nt][3],
                             l0, l1, l2, l3, bh0[nt], bh1[nt]);
            }
        }

        #pragma unroll
        for (int mt = 0; mt < 2; ++mt)
            #pragma unroll
            for (int nt = 0; nt < 4; ++nt) {
                dmax[mt*2+0] = fmaxf(dmax[mt*2+0], fmaxf(d[mt][nt][0], d[mt][nt][1]));
                dmax[mt*2+1] = fmaxf(dmax[mt*2+1], fmaxf(d[mt][nt][2], d[mt][nt][3]));
            }
    }

    #pragma unroll
    for (int e = 0; e < 4; ++e) {
        dmax[e] = fmaxf(dmax[e], __shfl_xor_sync(0xffffffffu, dmax[e], 1));
        dmax[e] = fmaxf(dmax[e], __shfl_xor_sync(0xffffffffu, dmax[e], 2));
    }
    if (j == 0) {
        #pragma unroll
        for (int mt = 0; mt < 2; ++mt)
            #pragma unroll
            for (int hf = 0; hf < 2; ++hf) {
                int ch = warp * 32 + mt * 16 + hf * 8 + g;
                g_pool[(enc * B_ + b) * D_ + ch] = fmaxf(dmax[mt*2+hf] + b3[ch], 0.f);
            }
    }
}

// ---------------------------------------------------------------------------
// Kernel 2: fused fc + distances + exact top-10. grid 64, 256 threads.
// ---------------------------------------------------------------------------
__global__ __launch_bounds__(256, 1)
void k_fcdist(const float* __restrict__ teWf, const float* __restrict__ tebf,
              const float* __restrict__ reWf, const float* __restrict__ rebf,
              const float* __restrict__ decW1)
{
    const int b = blockIdx.x, t = threadIdx.x;
    __shared__ float ste[256], rets[256], stgt[256];
    __shared__ float d[1024];
    __shared__ float sval[256];
    __shared__ int   sidx[256];

    ste[t] = g_pool[b * D_ + t];
    d[t]   = g_pool[(B_ + b) * D_ + t];     // sre scratch
    __syncthreads();

    float a = tebf[t], r = rebf[t];
    #pragma unroll 8
    for (int i = 0; i < 256; ++i) {
        a = fmaf(ste[i], teWf[i * 256 + t], a);
        r = fmaf(d[i],   reWf[i * 256 + t], r);
    }
    rets[t] = r;
    stgt[t] = a;
    __syncthreads();

    float tv = 0.f;
    #pragma unroll 8
    for (int i = 0; i < 256; ++i)
        tv = fmaf(stgt[i], decW1[i * 256 + t], tv);
    g_T[b * D_ + t] = tv;

    // distances (coalesced, 4 sources/thread)
    const int s4 = 4 * t;
    float a0 = 0.f, a1 = 0.f, a2 = 0.f, a3 = 0.f;
    #pragma unroll 4
    for (int k = 0; k < 256; ++k) {
        float rr = rets[k];
        float4 v = *(const float4*)&g_varT[k * S_ + s4];
        float4 c = *(const float4*)&g_rscT[k * S_ + s4];
        float d0 = rr - c.x, d1 = rr - c.y, d2 = rr - c.z, d3 = rr - c.w;
        a0 = fmaf(v.x, d0 * d0, a0);
        a1 = fmaf(v.y, d1 * d1, a1);
        a2 = fmaf(v.z, d2 * d2, a2);
        a3 = fmaf(v.w, d3 * d3, a3);
    }
    d[s4] = a0; d[s4 + 1] = a1; d[s4 + 2] = a2; d[s4 + 3] = a3;
    __syncthreads();

    for (int it = 0; it < KRET; ++it) {
        float bv = 1e30f; int bi = S_;
        #pragma unroll
        for (int q = 0; q < 4; ++q) {
            int s = q * 256 + t;
            float v = d[s];
            if (v < bv || (v == bv && s < bi)) { bv = v; bi = s; }
        }
        sval[t] = bv; sidx[t] = bi;
        __syncthreads();
        for (int off = 128; off > 0; off >>= 1) {
            if (t < off) {
                float v2 = sval[t + off]; int i2 = sidx[t + off];
                if (v2 < sval[t] || (v2 == sval[t] && i2 < sidx[t])) {
                    sval[t] = v2; sidx[t] = i2;
                }
            }
            __syncthreads();
        }
        if (t == 0) {
            g_idx[b * KRET + it] = sidx[0];
            d[sidx[0]] = 1e30f;
        }
        __syncthreads();
    }
}

// ---------------------------------------------------------------------------
// Kernel 4: decoder MLP -> params[96] per (b,k). 4 CTAs/SM.
// ---------------------------------------------------------------------------
__global__ __launch_bounds__(256, 4)
void k_decode_mlp(const float* __restrict__ decW2, const float* __restrict__ decb2,
                  const float* __restrict__ decW3, const float* __restrict__ decb3,
                  const float* __restrict__ proj,  const float* __restrict__ defp)
{
    const int bk = blockIdx.x;
    const int b = bk / KRET;
    const int t = threadIdx.x;
    const int s = g_idx[bk];

    __shared__ __align__(16) u64 H1p[256][10];
    __shared__ __align__(16) u64 H2p[256][10];
    __shared__ float raw[NPAR];

    {
        float base = g_T[b * D_ + t] + g_SC1[s * 256 + t];
        const float* p1 = &g_P1[s * (NPART * 256) + t];
        #pragma unroll
        for (int pr = 0; pr < 8; ++pr) {
            float lo = fmaxf(base + p1[(2 * pr) * 256], 0.f);
            float hi = fmaxf(base + p1[(2 * pr + 1) * 256], 0.f);
            H1p[t][pr] = pk(lo, hi);
        }
    }
    __syncthreads();

    const int c0 = (t & 63) * 4, pg = t >> 6;

    {
        u64 acc[2][4];
        float4 bb = *(const float4*)&decb2[c0];
        acc[0][0] = acc[1][0] = pk(bb.x, bb.x);
        acc[0][1] = acc[1][1] = pk(bb.y, bb.y);
        acc[0][2] = acc[1][2] = pk(bb.z, bb.z);
        acc[0][3] = acc[1][3] = pk(bb.w, bb.w);
        #pragma unroll 4
        for (int k = 0; k < 256; ++k) {
            ulonglong2 xx = *(const ulonglong2*)&H1p[k][pg * 2];
            float4 w = *(const float4*)&decW2[k * 256 + c0];
            u64 wp0 = pk(w.x, w.x), wp1 = pk(w.y, w.y);
            u64 wp2 = pk(w.z, w.z), wp3 = pk(w.w, w.w);
            acc[0][0] = fma2(xx.x, wp0, acc[0][0]);
            acc[0][1] = fma2(xx.x, wp1, acc[0][1]);
            acc[0][2] = fma2(xx.x, wp2, acc[0][2]);
            acc[0][3] = fma2(xx.x, wp3, acc[0][3]);
            acc[1][0] = fma2(xx.y, wp0, acc[1][0]);
            acc[1][1] = fma2(xx.y, wp1, acc[1][1]);
            acc[1][2] = fma2(xx.y, wp2, acc[1][2]);
            acc[1][3] = fma2(xx.y, wp3, acc[1][3]);
        }
        #pragma unroll
        for (int jj = 0; jj < 4; ++jj) {
            #pragma unroll
            for (int q = 0; q < 2; ++q) {
                float lo, hi; upk(acc[q][jj], lo, hi);
                lo = fmaxf(lo, 0.f); hi = fmaxf(hi, 0.f);
                H2p[c0 + jj][pg * 2 + q] = pk(lo, hi);
            }
        }
    }
    __syncthreads();

    const float* H2f = (const float*)H2p;
    if (t < NPAR) {
        const int p = t / 6, o = t % 6;
        float v = decb3[o];
        #pragma unroll 8
        for (int k = 0; k < 256; ++k)
            v = fmaf(H2f[k * 20 + p], decW3[k * 6 + o], v);
        raw[t] = v;
    }
    __syncthreads();

    if (t < NPAR) {
        float v = defp[s * NPAR + t];
        const float* pr = proj + (size_t)s * NPAR * NPAR + t * NPAR;
        #pragma unroll 8
        for (int jj = 0; jj < NPAR; ++jj)
            v = fmaf(pr[jj], raw[jj], v);
        g_par[bk * NPAR + t] = v;
    }
}

// ---------------------------------------------------------------------------
// Kernel 5: deformation (round-12 smem-staged form). grid (640, 6).
// ---------------------------------------------------------------------------
__global__ __launch_bounds__(256)
void k_deform(const float* __restrict__ mat, float* __restrict__ out)
{
    const int bk = blockIdx.x;
    const int t = threadIdx.x;
    const int s = g_idx[bk];
    __shared__ float par[NPAR];
    __shared__ __align__(16) float tilebuf[64 * 104];
    if (t < NPAR) par[t] = g_par[bk * NPAR + t];

    const float* mb = mat + (size_t)s * PSRC3 * NPAR;
    float* ob = out + (size_t)bk * PSRC3;
    const int row = t >> 2, q = t & 3;

    #pragma unroll 1
    for (int tile = 0; tile < 4; ++tile) {
        const int R0 = blockIdx.y * 256 + tile * 64;
        __syncthreads();
        const float4* src = (const float4*)(mb + (size_t)R0 * NPAR);
        #pragma unroll
        for (int i = 0; i < 6; ++i) {
            int idx = i * 256 + t;
            int r = idx / 24, c = idx % 24;
            *(float4*)&tilebuf[r * 104 + c * 4] = src[idx];
        }
        __syncthreads();
        float v = 0.f;
        const float* tb = &tilebuf[row * 104 + q * 24];
        const float* pq = &par[q * 24];
        #pragma unroll
        for (int i4 = 0; i4 < 6; ++i4) {
            float4 m4 = *(const float4*)&tb[i4 * 4];
            v = fmaf(m4.x, pq[i4 * 4 + 0], v);
            v = fmaf(m4.y, pq[i4 * 4 + 1], v);
            v = fmaf(m4.z, pq[i4 * 4 + 2], v);
            v = fmaf(m4.w, pq[i4 * 4 + 3], v);
        }
        v += __shfl_xor_sync(0xffffffffu, v, 1);
        v += __shfl_xor_sync(0xffffffffu, v, 2);
        if (q == 0)
            ob[R0 + row] = v;
    }
}

// ---------------------------------------------------------------------------
extern "C" void kernel_launch(void* const* d_in, const int* in_sizes, int n_in,
                              void* d_out, int out_size)
{
    const float* noc  = (const float*)d_in[0];
    const float* teW1 = (const float*)d_in[1];  const float* teb1 = (const float*)d_in[2];
    const float* teW2 = (const float*)d_in[3];  const float* teb2 = (const float*)d_in[4];
    const float* teW3 = (const float*)d_in[5];  const float* teb3 = (const float*)d_in[6];
    const float* teWf = (const float*)d_in[7];  const float* tebf = (const float*)d_in[8];
    const float* reW1 = (const float*)d_in[9];  const float* reb1 = (const float*)d_in[10];
    const float* reW2 = (const float*)d_in[11]; const float* reb2 = (const float*)d_in[12];
    const float* reW3 = (const float*)d_in[13]; const float* reb3 = (const float*)d_in[14];
    const float* reWf = (const float*)d_in[15]; const float* rebf = (const float*)d_in[16];
    const float* decW1 = (const float*)d_in[17]; const float* decb1 = (const float*)d_in[18];
    const float* decW2 = (const float*)d_in[19]; const float* decb2 = (const float*)d_in[20];
    const float* decW3 = (const float*)d_in[21]; const float* decb3 = (const float*)d_in[22];
    const float* ret_src = (const float*)d_in[23];
    const float* src_codes = (const float*)d_in[24];
    const float* src_var = (const float*)d_in[25];
    const float* part_latent = (const float*)d_in[26];
    const float* defp = (const float*)d_in[27];
    const float* proj = (const float*)d_in[28];
    const float* mat  = (const float*)d_in[29];
    float* out = (float*)d_out;

    cudaFuncSetAttribute(k_pointnet, cudaFuncAttributeMaxDynamicSharedMemorySize, SMEMSZ);

    k_prep<<<1728, 256>>>(src_var, ret_src, teW3, reW3, teW2, reW2,
                          src_codes, decW1, decb1, part_latent);
    dim3 g1(B_, 2);
    k_pointnet<<<g1, 256, SMEMSZ>>>(noc, teW1, teb1, teb2, teb3,
                                    reW1, reb1, reb2, reb3);
    k_fcdist<<<B_, 256>>>(teWf, tebf, reWf, rebf, decW1);
    k_decode_mlp<<<B_ * KRET, 256>>>(decW2, decb2, decW3, decb3, proj, defp);
    dim3 g5(B_ * KRET, 6);
    k_deform<<<g5, 256>>>(mat, out);
}

// round 15
// speedup vs baseline: 1.1571x; 1.1571x over previous
#include <cuda_runtime.h>
#include <cuda_bf16.h>
#include <cstdint>

// ---------------------------------------------------------------------------
// JointRetriveDeformHead — round 14
//  * pointnet REVERTED to round-12 form (H2 scalar fp32; H3 on mma.sync).
//  * k_decode_mlp H2 (256->256) moved to mma.sync (3-limb bf16):
//    A = H1 limbs [16pt x 256k] smem, B = decW2 limbs prepacked
//    fragment-grouped [ks][ch][16] (2 L1 wavefronts per B-LDG, 4x cut),
//    D -> bias+relu -> H2f[ch][20] (raw/proj stages unchanged).
//  * k_prep fusion kept (+decW2 limb prepack blocks), k_fcdist kept.
// ---------------------------------------------------------------------------

#define B_      64
#define S_      1024
#define D_      256
#define KRET    10
#define NPART   16
#define NPAR    96
#define PSRC3   1536

__device__ float g_pool[2 * B_ * D_];
__device__ float g_T   [B_ * D_];
__device__ int   g_idx [B_ * KRET];
__device__ float g_par [B_ * KRET * NPAR];
__device__ float g_SC1 [S_ * D_];
__device__ float g_P1  [S_ * NPART * D_];
__device__ float g_varT[D_ * S_];
__device__ float g_rscT[D_ * S_];
__device__ unsigned short g_A3h[2 * 256 * 128];   // W3^T hi limb [enc][ch][k]
__device__ unsigned short g_A3l[2 * 256 * 128];   // W3^T lo limb
__device__ unsigned short g_dW2h[256 * 256];      // decW2 limbs [ks][ch][16kin]
__device__ unsigned short g_dW2l[256 * 256];

typedef unsigned long long u64;

__device__ __forceinline__ u64 pk(float lo, float hi) {
    u64 r; asm("mov.b64 %0,{%1,%2};" : "=l"(r) : "f"(lo), "f"(hi)); return r;
}
__device__ __forceinline__ void upk(u64 v, float& lo, float& hi) {
    asm("mov.b64 {%0,%1},%2;" : "=f"(lo), "=f"(hi) : "l"(v));
}
__device__ __forceinline__ u64 fma2(u64 a, u64 b, u64 c) {
    u64 d; asm("fma.rn.f32x2 %0,%1,%2,%3;" : "=l"(d) : "l"(a), "l"(b), "l"(c)); return d;
}
__device__ __forceinline__ void split_bf16(float v, unsigned short& h, unsigned short& l) {
    __nv_bfloat16 bh = __float2bfloat16(v);
    float fh = __bfloat162float(bh);
    __nv_bfloat16 bl = __float2bfloat16(v - fh);
    h = __bfloat16_as_ushort(bh);
    l = __bfloat16_as_ushort(bl);
}

#define MMA16816(d0,d1,d2,d3,a0,a1,a2,a3,b0,b1) \
    asm volatile("mma.sync.aligned.m16n8k16.row.col.f32.bf16.bf16.f32 " \
        "{%0,%1,%2,%3}, {%4,%5,%6,%7}, {%8,%9}, {%0,%1,%2,%3};" \
        : "+f"(d0),"+f"(d1),"+f"(d2),"+f"(d3) \
        : "r"(a0),"r"(a1),"r"(a2),"r"(a3),"r"(b0),"r"(b1))

// pointnet dynamic smem layout (bytes) — round-8/12 form
#define OFF_ALO 0          // u16 [256][136]  = 69632
#define OFF_BH  69632      // u16 [32][136]   = 8704
#define OFF_BL  78336      // u16 [32][136]   = 8704
#define OFF_H1  87040      // float [64][36]  = 9216
#define OFF_X   96256      // float [3][32]   = 384
#define SMEMSZ  96640

// ---------------------------------------------------------------------------
// k_prep — fused prep work, role by blockIdx.x. grid 1920, 256 threads.
//  [0,256)     transpose var/rsc -> [k][s]
//  [256,512)   W3 limb prepack (pointnet H3)
//  [512,768)   decW2 limb prepack (fragment-grouped)
//  [768,896)   SC1 (8 sources per block)
//  [896,1920)  P1 (1 source per block)
// ---------------------------------------------------------------------------
__global__ __launch_bounds__(256)
void k_prep(const float* __restrict__ var,  const float* __restrict__ rsc,
            const float* __restrict__ teW3, const float* __restrict__ reW3,
            const float* __restrict__ decW2,
            const float* __restrict__ src_codes,
            const float* __restrict__ decW1, const float* __restrict__ decb1,
            const float* __restrict__ part_latent)
{
    __shared__ __align__(16) char prepsm[8448];
    const int bid = blockIdx.x, t = threadIdx.x;

    if (bid < 256) {
        float (*tv)[33] = (float(*)[33])prepsm;
        float (*tr)[33] = (float(*)[33])(prepsm + 4224);
        const int tx = t & 31, ty = t >> 5;
        const int s0 = (bid & 31) * 32, k0 = (bid >> 5) * 32;
        #pragma unroll
        for (int jj = 0; jj < 4; ++jj) {
            int s = s0 + ty + jj * 8;
            tv[ty + jj * 8][tx] = var[s * D_ + k0 + tx];
            tr[ty + jj * 8][tx] = rsc[s * D_ + k0 + tx];
        }
        __syncthreads();
        #pragma unroll
        for (int jj = 0; jj < 4; ++jj) {
            int k = k0 + ty + jj * 8;
            g_varT[k * S_ + s0 + tx] = tv[tx][ty + jj * 8];
            g_rscT[k * S_ + s0 + tx] = tr[tx][ty + jj * 8];
        }
    } else if (bid < 512) {
        int idx = (bid - 256) * 256 + t;       // [0, 65536)
        int enc = idx >> 15;
        int r   = idx & 32767;
        int ch  = r >> 7;
        int k   = r & 127;
        const float* W3 = enc ? reW3 : teW3;
        float w = W3[k * 256 + ch];
        unsigned short h, l;
        split_bf16(w, h, l);
        g_A3h[idx] = h;
        g_A3l[idx] = l;
    } else if (bid < 768) {
        int idx = (bid - 512) * 256 + t;       // [0, 65536) = k*256+ch
        int k  = idx >> 8;
        int ch = idx & 255;
        float w = decW2[k * 256 + ch];
        unsigned short h, l;
        split_bf16(w, h, l);
        int ks = k >> 4, kin = k & 15;
        g_dW2h[(ks * 256 + ch) * 16 + kin] = h;
        g_dW2l[(ks * 256 + ch) * 16 + kin] = l;
    } else if (bid < 896) {
        float (*scs)[256] = (float(*)[256])prepsm;
        const int s0 = (bid - 768) * 8;
        #pragma unroll
        for (int q = 0; q < 8; ++q)
            scs[q][t] = src_codes[(s0 + q) * 256 + t];
        __syncthreads();
        float acc[8];
        float bb = decb1[t];
        #pragma unroll
        for (int q = 0; q < 8; ++q) acc[q] = bb;
        #pragma unroll 4
        for (int i = 0; i < 256; ++i) {
            float w = decW1[(256 + i) * 256 + t];
            #pragma unroll
            for (int q = 0; q < 8; ++q)
                acc[q] = fmaf(scs[q][i], w, acc[q]);
        }
        #pragma unroll
        for (int q = 0; q < 8; ++q)
            g_SC1[(s0 + q) * 256 + t] = acc[q];
    } else {
        float (*part)[32] = (float(*)[32])prepsm;
        const int s = bid - 896;
        ((float*)part)[t]       = part_latent[s * (NPART * 32) + t];
        ((float*)part)[t + 256] = part_latent[s * (NPART * 32) + t + 256];
        __syncthreads();
        float wt[32];
        #pragma unroll
        for (int i = 0; i < 32; ++i)
            wt[i] = decW1[(512 + i) * 256 + t];
        #pragma unroll 2
        for (int p = 0; p < NPART; ++p) {
            float v = 0.f;
            #pragma unroll
            for (int i = 0; i < 32; ++i)
                v = fmaf(part[p][i], wt[i], v);
            g_P1[(s * NPART + p) * 256 + t] = v;
        }
    }
}

// ---------------------------------------------------------------------------
// Kernel 1: PointNet (round-12 exact). grid (64,2), 256 threads.
// ---------------------------------------------------------------------------
__global__ __launch_bounds__(256, 1)
void k_pointnet(const float* __restrict__ noc,
                const float* __restrict__ teW1, const float* __restrict__ teb1,
                const float* __restrict__ teW2, const float* __restrict__ teb2,
                const float* __restrict__ teb3,
                const float* __restrict__ reW1, const float* __restrict__ reb1,
                const float* __restrict__ reW2, const float* __restrict__ reb2,
                const float* __restrict__ reb3)
{
    extern __shared__ char smem[];
    const int b = blockIdx.x;
    const int enc = blockIdx.y;
    const float* W1 = enc ? reW1 : teW1; const float* b1 = enc ? reb1 : teb1;
    const float* W2 = enc ? reW2 : teW2; const float* b2 = enc ? reb2 : teb2;
    const float* b3 = enc ? reb3 : teb3;

    const int t = threadIdx.x;
    const int warp = t >> 5, lane = t & 31;
    const int g = lane >> 2, j = lane & 3;

    unsigned short* ALO = (unsigned short*)(smem + OFF_ALO);
    unsigned short* BHs = (unsigned short*)(smem + OFF_BH);
    unsigned short* BLs = (unsigned short*)(smem + OFF_BL);
    float* H1c = (float*)(smem + OFF_H1);
    float* Xf  = (float*)(smem + OFF_X);
    const uint32_t* ALO32 = (const uint32_t*)ALO;
    const uint32_t* BH32  = (const uint32_t*)BHs;
    const uint32_t* BL32  = (const uint32_t*)BLs;

    {
        const uint4* src = (const uint4*)(g_A3l + enc * 32768);
        #pragma unroll
        for (int i = 0; i < 16; ++i)
            *(uint4*)(ALO + t * 136 + i * 8) = src[t * 16 + i];
    }

    uint32_t ahi[64];
    {
        const uint32_t* AH = (const uint32_t*)(g_A3h + enc * 32768);
        #pragma unroll
        for (int mt = 0; mt < 2; ++mt) {
            const int r0 = warp * 32 + mt * 16 + g;
            #pragma unroll
            for (int ks = 0; ks < 8; ++ks) {
                const int fi = (mt * 8 + ks) * 4;
                ahi[fi + 0] = AH[r0 * 64 + j + 8 * ks];
                ahi[fi + 1] = AH[(r0 + 8) * 64 + j + 8 * ks];
                ahi[fi + 2] = AH[r0 * 64 + j + 4 + 8 * ks];
                ahi[fi + 3] = AH[(r0 + 8) * 64 + j + 4 + 8 * ks];
            }
        }
    }

    const int colB = t & 63, pgB = t >> 6;
    const int c0C = (t & 31) * 4, pgC = t >> 5;
    const float w10 = W1[colB], w11 = W1[64 + colB], w12 = W1[128 + colB];
    const float bb1 = b1[colB];
    const float4 bb2 = *(const float4*)&b2[c0C];
    const u64 bb2p[4] = { pk(bb2.x, bb2.x), pk(bb2.y, bb2.y),
                          pk(bb2.z, bb2.z), pk(bb2.w, bb2.w) };

    float dmax[4] = { -1e30f, -1e30f, -1e30f, -1e30f };

    #pragma unroll 1
    for (int chunk = 0; chunk < 32; ++chunk) {
        __syncthreads();
        if (t < 96) {
            int c = t >> 5, p = t & 31;
            Xf[c * 32 + p] = noc[b * 3072 + c * 1024 + chunk * 32 + p];
        }
        __syncthreads();

        {
            float v[8];
            #pragma unroll
            for (int pp = 0; pp < 8; ++pp) {
                int p = pgB * 8 + pp;
                float h = fmaf(Xf[p], w10, fmaf(Xf[32 + p], w11, fmaf(Xf[64 + p], w12, bb1)));
                v[pp] = fmaxf(h, 0.f);
            }
            #pragma unroll
            for (int q = 0; q < 4; ++q)
                *(u64*)&H1c[colB * 36 + pgB * 8 + 2 * q] = pk(v[2*q], v[2*q+1]);
        }
        __syncthreads();

        {
            u64 acc[2][4];
            #pragma unroll
            for (int q = 0; q < 2; ++q)
                #pragma unroll
                for (int jj = 0; jj < 4; ++jj) acc[q][jj] = bb2p[jj];
            #pragma unroll 4
            for (int k = 0; k < 64; ++k) {
                ulonglong2 xa = *(const ulonglong2*)&H1c[k * 36 + pgC * 4];
                float4 w = *(const float4*)&W2[k * 128 + c0C];
                u64 wp0 = pk(w.x, w.x), wp1 = pk(w.y, w.y);
                u64 wp2 = pk(w.z, w.z), wp3 = pk(w.w, w.w);
                acc[0][0] = fma2(xa.x, wp0, acc[0][0]);
                acc[0][1] = fma2(xa.x, wp1, acc[0][1]);
                acc[0][2] = fma2(xa.x, wp2, acc[0][2]);
                acc[0][3] = fma2(xa.x, wp3, acc[0][3]);
                acc[1][0] = fma2(xa.y, wp0, acc[1][0]);
                acc[1][1] = fma2(xa.y, wp1, acc[1][1]);
                acc[1][2] = fma2(xa.y, wp2, acc[1][2]);
                acc[1][3] = fma2(xa.y, wp3, acc[1][3]);
            }
            float vals[4][4];
            #pragma unroll
            for (int q = 0; q < 2; ++q)
                #pragma unroll
                for (int jj = 0; jj < 4; ++jj)
                    upk(acc[q][jj], vals[2*q][jj], vals[2*q+1][jj]);
            #pragma unroll
            for (int p = 0; p < 4; ++p) {
                int n = pgC * 4 + p;
                unsigned short h[4], l[4];
                #pragma unroll
                for (int jj = 0; jj < 4; ++jj)
                    split_bf16(fmaxf(vals[p][jj], 0.f), h[jj], l[jj]);
                u64 hp = (u64)h[0] | ((u64)h[1] << 16) | ((u64)h[2] << 32) | ((u64)h[3] << 48);
                u64 lp = (u64)l[0] | ((u64)l[1] << 16) | ((u64)l[2] << 32) | ((u64)l[3] << 48);
                *(u64*)((char*)BHs + n * 272 + c0C * 2) = hp;
                *(u64*)((char*)BLs + n * 272 + c0C * 2) = lp;
            }
        }
        __syncthreads();

        float d[2][4][4];
        #pragma unroll
        for (int mt = 0; mt < 2; ++mt)
            #pragma unroll
            for (int nt = 0; nt < 4; ++nt)
                #pragma unroll
                for (int e = 0; e < 4; ++e) d[mt][nt][e] = 0.f;

        #pragma unroll
        for (int ks = 0; ks < 8; ++ks) {
            uint32_t bh0[4], bh1[4], bl0[4], bl1[4];
            #pragma unroll
            for (int nt = 0; nt < 4; ++nt) {
                const uint32_t* BHrow = BH32 + (nt * 8 + g) * 68;
                const uint32_t* BLrow = BL32 + (nt * 8 + g) * 68;
                bh0[nt] = BHrow[j + 8 * ks];
                bh1[nt] = BHrow[j + 4 + 8 * ks];
                bl0[nt] = BLrow[j + 8 * ks];
                bl1[nt] = BLrow[j + 4 + 8 * ks];
            }
            #pragma unroll
            for (int mt = 0; mt < 2; ++mt) {
                const int fi = (mt * 8 + ks) * 4;
                uint32_t a0 = ahi[fi], a1 = ahi[fi+1], a2 = ahi[fi+2], a3 = ahi[fi+3];
                #pragma unroll
                for (int nt = 0; nt < 4; ++nt) {
                    MMA16816(d[mt][nt][0], d[mt][nt][1], d[mt][nt][2], d[mt][nt][3],
                             a0, a1, a2, a3, bh0[nt], bh1[nt]);
                    MMA16816(d[mt][nt][0], d[mt][nt][1], d[mt][nt][2], d[mt][nt][3],
                             a0, a1, a2, a3, bl0[nt], bl1[nt]);
                }
                const int r0 = warp * 32 + mt * 16 + g;
                uint32_t l0 = ALO32[r0 * 68 + j + 8 * ks];
                uint32_t l1 = ALO32[(r0 + 8) * 68 + j + 8 * ks];
                uint32_t l2 = ALO32[r0 * 68 + j + 4 + 8 * ks];
                uint32_t l3 = ALO32[(r0 + 8) * 68 + j + 4 + 8 * ks];
                #pragma unroll
                for (int nt = 0; nt < 4; ++nt)
                    MMA16816(d[mt][nt][0], d[mt][nt][1], d[mt][nt][2], d[mt][nt][3],
                             l0, l1, l2, l3, bh0[nt], bh1[nt]);
            }
        }

        #pragma unroll
        for (int mt = 0; mt < 2; ++mt)
            #pragma unroll
            for (int nt = 0; nt < 4; ++nt) {
                dmax[mt*2+0] = fmaxf(dmax[mt*2+0], fmaxf(d[mt][nt][0], d[mt][nt][1]));
                dmax[mt*2+1] = fmaxf(dmax[mt*2+1], fmaxf(d[mt][nt][2], d[mt][nt][3]));
            }
    }

    #pragma unroll
    for (int e = 0; e < 4; ++e) {
        dmax[e] = fmaxf(dmax[e], __shfl_xor_sync(0xffffffffu, dmax[e], 1));
        dmax[e] = fmaxf(dmax[e], __shfl_xor_sync(0xffffffffu, dmax[e], 2));
    }
    if (j == 0) {
        #pragma unroll
        for (int mt = 0; mt < 2; ++mt)
            #pragma unroll
            for (int hf = 0; hf < 2; ++hf) {
                int ch = warp * 32 + mt * 16 + hf * 8 + g;
                g_pool[(enc * B_ + b) * D_ + ch] = fmaxf(dmax[mt*2+hf] + b3[ch], 0.f);
            }
    }
}

// ---------------------------------------------------------------------------
// Kernel 2: fused fc + distances + exact top-10. grid 64, 256 threads.
// ---------------------------------------------------------------------------
__global__ __launch_bounds__(256, 1)
void k_fcdist(const float* __restrict__ teWf, const float* __restrict__ tebf,
              const float* __restrict__ reWf, const float* __restrict__ rebf,
              const float* __restrict__ decW1)
{
    const int b = blockIdx.x, t = threadIdx.x;
    __shared__ float ste[256], rets[256], stgt[256];
    __shared__ float d[1024];
    __shared__ float sval[256];
    __shared__ int   sidx[256];

    ste[t] = g_pool[b * D_ + t];
    d[t]   = g_pool[(B_ + b) * D_ + t];
    __syncthreads();

    float a = tebf[t], r = rebf[t];
    #pragma unroll 8
    for (int i = 0; i < 256; ++i) {
        a = fmaf(ste[i], teWf[i * 256 + t], a);
        r = fmaf(d[i],   reWf[i * 256 + t], r);
    }
    rets[t] = r;
    stgt[t] = a;
    __syncthreads();

    float tv = 0.f;
    #pragma unroll 8
    for (int i = 0; i < 256; ++i)
        tv = fmaf(stgt[i], decW1[i * 256 + t], tv);
    g_T[b * D_ + t] = tv;

    const int s4 = 4 * t;
    float a0 = 0.f, a1 = 0.f, a2 = 0.f, a3 = 0.f;
    #pragma unroll 4
    for (int k = 0; k < 256; ++k) {
        float rr = rets[k];
        float4 v = *(const float4*)&g_varT[k * S_ + s4];
        float4 c = *(const float4*)&g_rscT[k * S_ + s4];
        float d0 = rr - c.x, d1 = rr - c.y, d2 = rr - c.z, d3 = rr - c.w;
        a0 = fmaf(v.x, d0 * d0, a0);
        a1 = fmaf(v.y, d1 * d1, a1);
        a2 = fmaf(v.z, d2 * d2, a2);
        a3 = fmaf(v.w, d3 * d3, a3);
    }
    d[s4] = a0; d[s4 + 1] = a1; d[s4 + 2] = a2; d[s4 + 3] = a3;
    __syncthreads();

    for (int it = 0; it < KRET; ++it) {
        float bv = 1e30f; int bi = S_;
        #pragma unroll
        for (int q = 0; q < 4; ++q) {
            int s = q * 256 + t;
            float v = d[s];
            if (v < bv || (v == bv && s < bi)) { bv = v; bi = s; }
        }
        sval[t] = bv; sidx[t] = bi;
        __syncthreads();
        for (int off = 128; off > 0; off >>= 1) {
            if (t < off) {
                float v2 = sval[t + off]; int i2 = sidx[t + off];
                if (v2 < sval[t] || (v2 == sval[t] && i2 < sidx[t])) {
                    sval[t] = v2; sidx[t] = i2;
                }
            }
            __syncthreads();
        }
        if (t == 0) {
            g_idx[b * KRET + it] = sidx[0];
            d[sidx[0]] = 1e30f;
        }
        __syncthreads();
    }
}

// ---------------------------------------------------------------------------
// Kernel 4: decoder MLP via mma.sync. grid 640, 256 threads, 4 CTAs/SM.
// H2: D[16 parts x 256 ch] = H1limbs[16x256] x decW2limbs (3 passes).
// ---------------------------------------------------------------------------
__global__ __launch_bounds__(256, 4)
void k_decode_mlp(const float* __restrict__ decb2,
                  const float* __restrict__ decW3, const float* __restrict__ decb3,
                  const float* __restrict__ proj,  const float* __restrict__ defp)
{
    const int bk = blockIdx.x;
    const int b = bk / KRET;
    const int t = threadIdx.x;
    const int s = g_idx[bk];
    const int warp = t >> 5, lane = t & 31;
    const int g = lane >> 2, j = lane & 3;

    __shared__ __align__(16) unsigned short AH1[16 * 264];  // [part][k pad264]
    __shared__ __align__(16) unsigned short AL1[16 * 264];
    __shared__ float H2f[256 * 20];                          // [ch][part pad20]
    __shared__ float raw[NPAR];

    // ---- H1: base + P1, relu, split limbs into A tiles (k-col = t) ----
    {
        float base = g_T[b * D_ + t] + g_SC1[s * 256 + t];
        const float* p1 = &g_P1[s * (NPART * 256) + t];
        #pragma unroll
        for (int p = 0; p < NPART; ++p) {
            float v = fmaxf(base + p1[p * 256], 0.f);
            unsigned short h, l;
            split_bf16(v, h, l);
            AH1[p * 264 + t] = h;
            AL1[p * 264 + t] = l;
        }
    }
    __syncthreads();

    // ---- H2 via MMA: warp handles n=32 chs (4 n8-tiles), k=256 (16 ksteps) ----
    {
        const uint32_t* A1H32 = (const uint32_t*)AH1;   // [16][132]
        const uint32_t* A1L32 = (const uint32_t*)AL1;
        const uint32_t* WH32 = (const uint32_t*)g_dW2h; // [(ks*256+ch)*8]
        const uint32_t* WL32 = (const uint32_t*)g_dW2l;
        const int chb = warp * 32;

        float d[4][4];
        #pragma unroll
        for (int nt = 0; nt < 4; ++nt)
            #pragma unroll
            for (int e = 0; e < 4; ++e) d[nt][e] = 0.f;

        #pragma unroll 4
        for (int ks = 0; ks < 16; ++ks) {
            uint32_t ah0 = A1H32[g * 132 + j + 8 * ks];
            uint32_t ah1 = A1H32[(g + 8) * 132 + j + 8 * ks];
            uint32_t ah2 = A1H32[g * 132 + j + 4 + 8 * ks];
            uint32_t ah3 = A1H32[(g + 8) * 132 + j + 4 + 8 * ks];
            uint32_t al0 = A1L32[g * 132 + j + 8 * ks];
            uint32_t al1 = A1L32[(g + 8) * 132 + j + 8 * ks];
            uint32_t al2 = A1L32[g * 132 + j + 4 + 8 * ks];
            uint32_t al3 = A1L32[(g + 8) * 132 + j + 4 + 8 * ks];
            #pragma unroll
            for (int nt = 0; nt < 4; ++nt) {
                const int ch = chb + nt * 8 + g;
                const uint32_t* Wh = WH32 + (ks * 256 + ch) * 8;
                const uint32_t* Wl = WL32 + (ks * 256 + ch) * 8;
                uint32_t bh0 = Wh[j], bh1 = Wh[j + 4];
                uint32_t bl0 = Wl[j], bl1 = Wl[j + 4];
                MMA16816(d[nt][0], d[nt][1], d[nt][2], d[nt][3],
                         ah0, ah1, ah2, ah3, bh0, bh1);
                MMA16816(d[nt][0], d[nt][1], d[nt][2], d[nt][3],
                         ah0, ah1, ah2, ah3, bl0, bl1);
                MMA16816(d[nt][0], d[nt][1], d[nt][2], d[nt][3],
                         al0, al1, al2, al3, bh0, bh1);
            }
        }

        // epilogue: bias + relu -> H2f[ch][part]
        #pragma unroll
        for (int nt = 0; nt < 4; ++nt) {
            const int ch0 = chb + nt * 8 + 2 * j;
            float bb0 = decb2[ch0], bb1 = decb2[ch0 + 1];
            H2f[ch0 * 20 + g]           = fmaxf(d[nt][0] + bb0, 0.f);
            H2f[(ch0 + 1) * 20 + g]     = fmaxf(d[nt][1] + bb1, 0.f);
            H2f[ch0 * 20 + g + 8]       = fmaxf(d[nt][2] + bb0, 0.f);
            H2f[(ch0 + 1) * 20 + g + 8] = fmaxf(d[nt][3] + bb1, 0.f);
        }
    }
    __syncthreads();

    // ---- raw = H2 @ W3 + b3 ----
    if (t < NPAR) {
        const int p = t / 6, o = t % 6;
        float v = decb3[o];
        #pragma unroll 8
        for (int k = 0; k < 256; ++k)
            v = fmaf(H2f[k * 20 + p], decW3[k * 6 + o], v);
        raw[t] = v;
    }
    __syncthreads();

    // ---- params = proj[s] @ raw + def[s] ----
    if (t < NPAR) {
        float v = defp[s * NPAR + t];
        const float* pr = proj + (size_t)s * NPAR * NPAR + t * NPAR;
        #pragma unroll 8
        for (int jj = 0; jj < NPAR; ++jj)
            v = fmaf(pr[jj], raw[jj], v);
        g_par[bk * NPAR + t] = v;
    }
}

// ---------------------------------------------------------------------------
// Kernel 5: deformation (round-12 smem-staged form). grid (640, 6).
// ---------------------------------------------------------------------------
__global__ __launch_bounds__(256)
void k_deform(const float* __restrict__ mat, float* __restrict__ out)
{
    const int bk = blockIdx.x;
    const int t = threadIdx.x;
    const int s = g_idx[bk];
    __shared__ float par[NPAR];
    __shared__ __align__(16) float tilebuf[64 * 104];
    if (t < NPAR) par[t] = g_par[bk * NPAR + t];

    const float* mb = mat + (size_t)s * PSRC3 * NPAR;
    float* ob = out + (size_t)bk * PSRC3;
    const int row = t >> 2, q = t & 3;

    #pragma unroll 1
    for (int tile = 0; tile < 4; ++tile) {
        const int R0 = blockIdx.y * 256 + tile * 64;
        __syncthreads();
        const float4* src = (const float4*)(mb + (size_t)R0 * NPAR);
        #pragma unroll
        for (int i = 0; i < 6; ++i) {
            int idx = i * 256 + t;
            int r = idx / 24, c = idx % 24;
            *(float4*)&tilebuf[r * 104 + c * 4] = src[idx];
        }
        __syncthreads();
        float v = 0.f;
        const float* tb = &tilebuf[row * 104 + q * 24];
        const float* pq = &par[q * 24];
        #pragma unroll
        for (int i4 = 0; i4 < 6; ++i4) {
            float4 m4 = *(const float4*)&tb[i4 * 4];
            v = fmaf(m4.x, pq[i4 * 4 + 0], v);
            v = fmaf(m4.y, pq[i4 * 4 + 1], v);
            v = fmaf(m4.z, pq[i4 * 4 + 2], v);
            v = fmaf(m4.w, pq[i4 * 4 + 3], v);
        }
        v += __shfl_xor_sync(0xffffffffu, v, 1);
        v += __shfl_xor_sync(0xffffffffu, v, 2);
        if (q == 0)
            ob[R0 + row] = v;
    }
}

// ---------------------------------------------------------------------------
extern "C" void kernel_launch(void* const* d_in, const int* in_sizes, int n_in,
                              void* d_out, int out_size)
{
    const float* noc  = (const float*)d_in[0];
    const float* teW1 = (const float*)d_in[1];  const float* teb1 = (const float*)d_in[2];
    const float* teW2 = (const float*)d_in[3];  const float* teb2 = (const float*)d_in[4];
    const float* teW3 = (const float*)d_in[5];  const float* teb3 = (const float*)d_in[6];
    const float* teWf = (const float*)d_in[7];  const float* tebf = (const float*)d_in[8];
    const float* reW1 = (const float*)d_in[9];  const float* reb1 = (const float*)d_in[10];
    const float* reW2 = (const float*)d_in[11]; const float* reb2 = (const float*)d_in[12];
    const float* reW3 = (const float*)d_in[13]; const float* reb3 = (const float*)d_in[14];
    const float* reWf = (const float*)d_in[15]; const float* rebf = (const float*)d_in[16];
    const float* decW1 = (const float*)d_in[17]; const float* decb1 = (const float*)d_in[18];
    const float* decW2 = (const float*)d_in[19]; const float* decb2 = (const float*)d_in[20];
    const float* decW3 = (const float*)d_in[21]; const float* decb3 = (const float*)d_in[22];
    const float* ret_src = (const float*)d_in[23];
    const float* src_codes = (const float*)d_in[24];
    const float* src_var = (const float*)d_in[25];
    const float* part_latent = (const float*)d_in[26];
    const float* defp = (const float*)d_in[27];
    const float* proj = (const float*)d_in[28];
    const float* mat  = (const float*)d_in[29];
    float* out = (float*)d_out;

    cudaFuncSetAttribute(k_pointnet, cudaFuncAttributeMaxDynamicSharedMemorySize, SMEMSZ);

    k_prep<<<1920, 256>>>(src_var, ret_src, teW3, reW3, decW2,
                          src_codes, decW1, decb1, part_latent);
    dim3 g1(B_, 2);
    k_pointnet<<<g1, 256, SMEMSZ>>>(noc, teW1, teb1, teW2, teb2, teb3,
                                    reW1, reb1, reW2, reb2, reb3);
    k_fcdist<<<B_, 256>>>(teWf, tebf, reWf, rebf, decW1);
    k_decode_mlp<<<B_ * KRET, 256>>>(decb2, decW3, decb3, proj, defp);
    dim3 g5(B_ * KRET, 6);
    k_deform<<<g5, 256>>>(mat, out);
}